// round 3
// baseline (speedup 1.0000x reference)
#include <cuda_runtime.h>
#include <math.h>

// ---------------------------------------------------------------------------
// ReplacementPolicyHead — Round 1 baseline (fp32 SIMT, packed f32x2 FMA)
//
// Pipeline:
//   A) g_H  = mish(x @ W1 + b1)        M=131072, N=768, K=768
//   B) g_QK = h @ [Wq | Wk] + [bq|bk]  M=131072, N=128, K=768
//   C) per-batch: scores = q k^T * 0.125, promotion head, gather by indices
// Scratch via __device__ globals (no allocations, graph-capturable).
// ---------------------------------------------------------------------------

#define B_BATCH   2048
#define SEQ       64
#define DMODEL    768
#define DPOL      64
#define M_ROWS    (B_BATCH * SEQ)        // 131072

__device__ float g_H [M_ROWS * DMODEL];  // 402 MB scratch
__device__ float g_QK[M_ROWS * 128];     // 67 MB scratch (q cols 0..63, k cols 64..127)

// ---- packed f32x2 helpers --------------------------------------------------
__device__ __forceinline__ unsigned long long pack2(float x, float y) {
    unsigned long long r;
    asm("mov.b64 %0, {%1, %2};" : "=l"(r) : "f"(x), "f"(y));
    return r;
}
__device__ __forceinline__ void ffma2(unsigned long long& d,
                                      unsigned long long a,
                                      unsigned long long b) {
    asm("fma.rn.f32x2 %0, %1, %2, %0;" : "+l"(d) : "l"(a), "l"(b));
}
__device__ __forceinline__ float2 unpack2(unsigned long long v) {
    float2 r;
    asm("mov.b64 {%0, %1}, %2;" : "=f"(r.x), "=f"(r.y) : "l"(v));
    return r;
}

__device__ __forceinline__ float mish_f(float c) {
    float sp = (c > 15.0f) ? c : log1pf(expf(c));
    return c * tanhf(sp);
}

// ---------------------------------------------------------------------------
// Kernel A: H = mish(X @ W1 + b1).  128x128 CTA tile, K-chunk 8,
// per-thread 8x8 via packed f32x2 accumulators.
// grid = (M/128, 768/128), block = 256
// ---------------------------------------------------------------------------
__global__ __launch_bounds__(256) void k_gemm_mish(
    const float* __restrict__ X, const float* __restrict__ W1,
    const float* __restrict__ b1)
{
    __shared__ float As[8][128];
    __shared__ float Bs[8][128];

    const int tid = threadIdx.x;
    const int tx  = tid & 15;          // 0..15 -> col group
    const int ty  = tid >> 4;          // 0..15 -> row group
    const int m0  = blockIdx.x * 128;
    const int n0  = blockIdx.y * 128;

    // loader indices
    const int a_row = tid >> 1;            // 0..127
    const int a_kk  = (tid & 1) * 4;       // 0 or 4
    const int b_kk  = tid >> 5;            // 0..7
    const int b_col = (tid & 31) * 4;      // 0..124

    unsigned long long acc[8][4];
#pragma unroll
    for (int i = 0; i < 8; i++)
#pragma unroll
        for (int j = 0; j < 4; j++) acc[i][j] = 0ULL;   // {0.f,0.f}

    for (int k0 = 0; k0 < DMODEL; k0 += 8) {
        float4 av = *(const float4*)&X[(size_t)(m0 + a_row) * DMODEL + k0 + a_kk];
        As[a_kk + 0][a_row] = av.x;
        As[a_kk + 1][a_row] = av.y;
        As[a_kk + 2][a_row] = av.z;
        As[a_kk + 3][a_row] = av.w;
        float4 bv = *(const float4*)&W1[(size_t)(k0 + b_kk) * DMODEL + n0 + b_col];
        *(float4*)&Bs[b_kk][b_col] = bv;
        __syncthreads();

#pragma unroll
        for (int kk = 0; kk < 8; kk++) {
            float4 a0 = *(const float4*)&As[kk][ty * 8];
            float4 a1 = *(const float4*)&As[kk][ty * 8 + 4];
            ulonglong2 bA = *(const ulonglong2*)&Bs[kk][tx * 8];
            ulonglong2 bB = *(const ulonglong2*)&Bs[kk][tx * 8 + 4];
            unsigned long long bb[4] = {bA.x, bA.y, bB.x, bB.y};
            float a[8] = {a0.x, a0.y, a0.z, a0.w, a1.x, a1.y, a1.z, a1.w};
#pragma unroll
            for (int ii = 0; ii < 8; ii++) {
                unsigned long long aa = pack2(a[ii], a[ii]);
#pragma unroll
                for (int j2 = 0; j2 < 4; j2++) ffma2(acc[ii][j2], aa, bb[j2]);
            }
        }
        __syncthreads();
    }

#pragma unroll
    for (int ii = 0; ii < 8; ii++) {
        int row = m0 + ty * 8 + ii;
#pragma unroll
        for (int j2 = 0; j2 < 4; j2++) {
            float2 v = unpack2(acc[ii][j2]);
            int n = n0 + tx * 8 + j2 * 2;
            float c0 = v.x + b1[n];
            float c1 = v.y + b1[n + 1];
            g_H[(size_t)row * DMODEL + n]     = mish_f(c0);
            g_H[(size_t)row * DMODEL + n + 1] = mish_f(c1);
        }
    }
}

// ---------------------------------------------------------------------------
// Kernel B: QK = H @ [Wq | Wk] + [bq | bk].  N = 128 (single col tile).
// grid = M/128, block = 256
// ---------------------------------------------------------------------------
__global__ __launch_bounds__(256) void k_gemm_qk(
    const float* __restrict__ Wq, const float* __restrict__ bq,
    const float* __restrict__ Wk, const float* __restrict__ bk)
{
    __shared__ float As[8][128];
    __shared__ float Bs[8][128];

    const int tid = threadIdx.x;
    const int tx  = tid & 15;
    const int ty  = tid >> 4;
    const int m0  = blockIdx.x * 128;

    const int a_row = tid >> 1;
    const int a_kk  = (tid & 1) * 4;
    const int b_kk  = tid >> 5;
    const int b_col = (tid & 31) * 4;

    unsigned long long acc[8][4];
#pragma unroll
    for (int i = 0; i < 8; i++)
#pragma unroll
        for (int j = 0; j < 4; j++) acc[i][j] = 0ULL;

    for (int k0 = 0; k0 < DMODEL; k0 += 8) {
        float4 av = *(const float4*)&g_H[(size_t)(m0 + a_row) * DMODEL + k0 + a_kk];
        As[a_kk + 0][a_row] = av.x;
        As[a_kk + 1][a_row] = av.y;
        As[a_kk + 2][a_row] = av.z;
        As[a_kk + 3][a_row] = av.w;
        const float* src = (b_col < 64)
            ? &Wq[(size_t)(k0 + b_kk) * DPOL + b_col]
            : &Wk[(size_t)(k0 + b_kk) * DPOL + (b_col - 64)];
        *(float4*)&Bs[b_kk][b_col] = *(const float4*)src;
        __syncthreads();

#pragma unroll
        for (int kk = 0; kk < 8; kk++) {
            float4 a0 = *(const float4*)&As[kk][ty * 8];
            float4 a1 = *(const float4*)&As[kk][ty * 8 + 4];
            ulonglong2 bA = *(const ulonglong2*)&Bs[kk][tx * 8];
            ulonglong2 bB = *(const ulonglong2*)&Bs[kk][tx * 8 + 4];
            unsigned long long bb[4] = {bA.x, bA.y, bB.x, bB.y};
            float a[8] = {a0.x, a0.y, a0.z, a0.w, a1.x, a1.y, a1.z, a1.w};
#pragma unroll
            for (int ii = 0; ii < 8; ii++) {
                unsigned long long aa = pack2(a[ii], a[ii]);
#pragma unroll
                for (int j2 = 0; j2 < 4; j2++) ffma2(acc[ii][j2], aa, bb[j2]);
            }
        }
        __syncthreads();
    }

#pragma unroll
    for (int ii = 0; ii < 8; ii++) {
        int row = m0 + ty * 8 + ii;
#pragma unroll
        for (int j2 = 0; j2 < 4; j2++) {
            float2 v = unpack2(acc[ii][j2]);
            int n = tx * 8 + j2 * 2;
            float bias0 = (n     < 64) ? bq[n]     : bk[n - 64];
            float bias1 = (n + 1 < 64) ? bq[n + 1] : bk[n + 1 - 64];
            g_QK[(size_t)row * 128 + n]     = v.x + bias0;
            g_QK[(size_t)row * 128 + n + 1] = v.y + bias1;
        }
    }
}

// ---------------------------------------------------------------------------
// Kernel C: per-batch scores + promotion + gather.
// grid = B, block = 256
// policy[0..4095]  = scores[i][j]              (i = idx/64, j = idx%64)
// policy[4096+p]   = scores[48+(p/3)/8][56+(p/3)%8] + prom2[p%24]
//   prom2[m] = k[56+m/3] . (Wp[:,m%3] + Wp[:,3]) + bp[m%3] + bp[3]
// ---------------------------------------------------------------------------
__global__ __launch_bounds__(256) void k_scores_gather(
    const float* __restrict__ Wp, const float* __restrict__ bp,
    const int* __restrict__ indices, float* __restrict__ out)
{
    __shared__ float q_s[64][65];
    __shared__ float k_s[64][65];
    __shared__ float s_s[64][64];
    __shared__ float prom2[24];

    const int b   = blockIdx.x;
    const int tid = threadIdx.x;

    for (int i = tid; i < 64 * 64; i += 256) {
        int r = i >> 6, c = i & 63;
        const float* row = &g_QK[((size_t)b * 64 + r) * 128];
        q_s[r][c] = row[c];
        k_s[r][c] = row[64 + c];
    }
    __syncthreads();

    for (int t = tid; t < 4096; t += 256) {
        int i = t >> 6, j = t & 63;
        float acc = 0.0f;
#pragma unroll
        for (int d = 0; d < 64; d++) acc += q_s[i][d] * k_s[j][d];
        s_s[i][j] = acc * 0.125f;
    }

    if (tid < 24) {
        int jr = 56 + tid / 3;
        int c  = tid % 3;
        float acc = bp[c] + bp[3];
#pragma unroll
        for (int d = 0; d < 64; d++)
            acc += k_s[jr][d] * (Wp[d * 4 + c] + Wp[d * 4 + 3]);
        prom2[tid] = acc;
    }
    __syncthreads();

    for (int t = tid; t < 1858; t += 256) {
        int id = indices[t];
        float v;
        if (id < 4096) {
            v = s_s[id >> 6][id & 63];
        } else {
            int p = id - 4096;
            int i = p / 3;
            v = s_s[48 + (i >> 3)][56 + (i & 7)] + prom2[p % 24];
        }
        out[(size_t)b * 1858 + t] = v;
    }
}

// ---------------------------------------------------------------------------
extern "C" void kernel_launch(void* const* d_in, const int* in_sizes, int n_in,
                              void* d_out, int out_size)
{
    const float* x   = (const float*)d_in[0];
    const float* W1  = (const float*)d_in[1];
    const float* b1  = (const float*)d_in[2];
    const float* Wq  = (const float*)d_in[3];
    const float* bq  = (const float*)d_in[4];
    const float* Wk  = (const float*)d_in[5];
    const float* bk  = (const float*)d_in[6];
    const float* Wp  = (const float*)d_in[7];
    const float* bp  = (const float*)d_in[8];
    const int*   idx = (const int*)d_in[9];

    dim3 gA(M_ROWS / 128, DMODEL / 128);   // (1024, 6)
    k_gemm_mish<<<gA, 256>>>(x, W1, b1);

    k_gemm_qk<<<M_ROWS / 128, 256>>>(Wq, bq, Wk, bk);

    k_scores_gather<<<B_BATCH, 256>>>(Wp, bp, idx, (float*)d_out);
}

// round 5
// speedup vs baseline: 2.1096x; 2.1096x over previous
#include <cuda_runtime.h>
#include <cuda_bf16.h>
#include <mma.h>
#include <math.h>

using namespace nvcuda;

#define B_BATCH 2048
#define DMODEL  768
#define M_ROWS  (B_BATCH * 64)   // 131072

typedef __nv_bfloat16 bf16;

__device__ bf16  g_Hhi[(size_t)M_ROWS * DMODEL];
__device__ bf16  g_Hlo[(size_t)M_ROWS * DMODEL];
__device__ float g_QK [(size_t)M_ROWS * 128];
__device__ bf16  g_W1T_hi[DMODEL * DMODEL];
__device__ bf16  g_W1T_lo[DMODEL * DMODEL];
__device__ bf16  g_WqkT_hi[128 * DMODEL];
__device__ bf16  g_WqkT_lo[128 * DMODEL];

// ---------------- helpers ----------------
__device__ __forceinline__ unsigned s2u(const void* p) {
    unsigned a;
    asm("{ .reg .u64 t; cvta.to.shared.u64 t, %1; cvt.u32.u64 %0, t; }" : "=r"(a) : "l"(p));
    return a;
}
__device__ __forceinline__ void cp16(unsigned dst, const void* src) {
    asm volatile("cp.async.cg.shared.global [%0], [%1], 16;" :: "r"(dst), "l"(src));
}
#define CP_COMMIT() asm volatile("cp.async.commit_group;" ::: "memory")
#define CP_WAIT0()  asm volatile("cp.async.wait_group 0;" ::: "memory")

__device__ __forceinline__ unsigned bf2u(__nv_bfloat162 v) { return *reinterpret_cast<unsigned*>(&v); }

// mish(x) = x*tanh(softplus(x)) = x*(t^2+2t)/(t^2+2t+2), t=e^x
__device__ __forceinline__ float mish_f(float x) {
    if (x > 40.0f) return x;
    float t = __expf(x);
    float u = t * t + 2.0f * t;
    return x * (u / (u + 2.0f));
}

// smem layout (kernels A/B): [0,512) bias; buf0 @512; buf1 @41472; each buf:
//   Ahi +0, Alo +10240, Bhi +20480, Blo +30720  (tiles 128 x 40 bf16, 80B rows)
#define TS        40            // tile row stride (elements)
#define TB        80            // tile row stride (bytes)
#define TILE_SZ   10240
#define BUF_SZ    40960
#define BUF0_OFF  512
#define BUF1_OFF  (512 + BUF_SZ)
#define SMEM_BYTES (512 + 2 * BUF_SZ)   // 82432
#define EPI_LD    132                   // epilogue float tile stride

// ---------------------------------------------------------------------------
// Weight transpose + bf16 split: src [K=768][N] fp32 -> dst [N][768] bf16.
// ---------------------------------------------------------------------------
__global__ void k_wconv(const float* __restrict__ src, int N, int mode)
{
    __shared__ float tile[32][33];
    int n0 = blockIdx.x * 32, k0 = blockIdx.y * 32;
    int tx = threadIdx.x, ty = threadIdx.y;
#pragma unroll
    for (int i = 0; i < 32; i += 8)
        tile[ty + i][tx] = src[(size_t)(k0 + ty + i) * N + n0 + tx];
    __syncthreads();
    bf16 *dhi, *dlo;
    if (mode == 0)      { dhi = g_W1T_hi;                dlo = g_W1T_lo; }
    else if (mode == 1) { dhi = g_WqkT_hi;               dlo = g_WqkT_lo; }
    else                { dhi = g_WqkT_hi + 64 * DMODEL; dlo = g_WqkT_lo + 64 * DMODEL; }
#pragma unroll
    for (int i = 0; i < 32; i += 8) {
        int n = n0 + ty + i, k = k0 + tx;
        float v = tile[tx][ty + i];
        bf16 h = __float2bfloat16(v);
        dhi[(size_t)n * DMODEL + k] = h;
        dlo[(size_t)n * DMODEL + k] = __float2bfloat16(v - __bfloat162float(h));
    }
}

// ---- shared compute core: 8 warps, warp (wm,wn) -> rows wm*32+32, cols wn*64+64
typedef wmma::fragment<wmma::matrix_a, 16, 16, 16, bf16, wmma::row_major> FragA;
typedef wmma::fragment<wmma::matrix_b, 16, 16, 16, bf16, wmma::col_major> FragB;
typedef wmma::fragment<wmma::accumulator, 16, 16, 16, float> FragC;

__device__ __forceinline__ void compute_chunk(const char* buf, int wm, int wn,
                                              FragC c[2][4])
{
    const bf16* Ah = (const bf16*)(buf);
    const bf16* Al = (const bf16*)(buf + TILE_SZ);
    const bf16* Bh = (const bf16*)(buf + 2 * TILE_SZ);
    const bf16* Bl = (const bf16*)(buf + 3 * TILE_SZ);
#pragma unroll
    for (int ks = 0; ks < 2; ks++) {
        FragA ah[2], al[2];
#pragma unroll
        for (int i = 0; i < 2; i++) {
            wmma::load_matrix_sync(ah[i], Ah + (wm * 32 + i * 16) * TS + ks * 16, TS);
            wmma::load_matrix_sync(al[i], Al + (wm * 32 + i * 16) * TS + ks * 16, TS);
        }
#pragma unroll
        for (int j = 0; j < 4; j++) {
            FragB bh, bl;
            wmma::load_matrix_sync(bh, Bh + (wn * 64 + j * 16) * TS + ks * 16, TS);
            wmma::load_matrix_sync(bl, Bl + (wn * 64 + j * 16) * TS + ks * 16, TS);
#pragma unroll
            for (int i = 0; i < 2; i++) {
                wmma::mma_sync(c[i][j], ah[i], bh, c[i][j]);
                wmma::mma_sync(c[i][j], ah[i], bl, c[i][j]);
                wmma::mma_sync(c[i][j], al[i], bh, c[i][j]);
            }
        }
    }
}

// stage weight (or bf16 activation) tile rows via cp.async: 4 x 16B per thread
__device__ __forceinline__ void stage_bf_pair(unsigned dst_hi, unsigned dst_lo,
                                              const bf16* __restrict__ shi,
                                              const bf16* __restrict__ slo)
{
    cp16(dst_hi,      shi);
    cp16(dst_hi + 16, shi + 8);
    cp16(dst_lo,      slo);
    cp16(dst_lo + 16, slo + 8);
}

// ---------------------------------------------------------------------------
// Kernel A: H = mish(X @ W1 + b1) -> g_Hhi/g_Hlo.  grid (6, 1024), 256 thr.
// ---------------------------------------------------------------------------
__global__ __launch_bounds__(256, 2) void k_gemmA(const float* __restrict__ X,
                                                  const float* __restrict__ b1)
{
    extern __shared__ char smem[];
    const unsigned sb = s2u(smem);
    float* bias = (float*)smem;
    const int tid = threadIdx.x, wid = tid >> 5;
    const int wm = wid & 3, wn = wid >> 2;
    const int n0 = blockIdx.x * 128, m0 = blockIdx.y * 128;
    const int r = tid >> 1, half = tid & 1;

    if (tid < 128) bias[tid] = b1[n0 + tid];

    FragC c[2][4];
#pragma unroll
    for (int i = 0; i < 2; i++)
#pragma unroll
        for (int j = 0; j < 4; j++) wmma::fill_fragment(c[i][j], 0.0f);

    const float* xrow = X + (size_t)(m0 + r) * DMODEL + half * 16;
    const bf16*  whr  = g_W1T_hi + (size_t)(n0 + r) * DMODEL + half * 16;
    const bf16*  wlr  = g_W1T_lo + (size_t)(n0 + r) * DMODEL + half * 16;
    const unsigned arow = r * TB + half * 32;   // byte offset of this thread's slot

    float4 xv[4];
    // prologue: chunk 0
    {
        const float4* xp = (const float4*)xrow;
#pragma unroll
        for (int p = 0; p < 4; p++) xv[p] = xp[p];
        stage_bf_pair(sb + BUF0_OFF + 2 * TILE_SZ + arow,
                      sb + BUF0_OFF + 3 * TILE_SZ + arow, whr, wlr);
        CP_COMMIT();
    }
    // convert+store chunk0 A
    {
        char* base = smem + BUF0_OFF;
#pragma unroll
        for (int p = 0; p < 2; p++) {
            float4 a = xv[2 * p], b = xv[2 * p + 1];
            __nv_bfloat162 h0 = __floats2bfloat162_rn(a.x, a.y);
            __nv_bfloat162 h1 = __floats2bfloat162_rn(a.z, a.w);
            __nv_bfloat162 h2 = __floats2bfloat162_rn(b.x, b.y);
            __nv_bfloat162 h3 = __floats2bfloat162_rn(b.z, b.w);
            __nv_bfloat162 l0 = __floats2bfloat162_rn(a.x - __bfloat162float(h0.x), a.y - __bfloat162float(h0.y));
            __nv_bfloat162 l1 = __floats2bfloat162_rn(a.z - __bfloat162float(h1.x), a.w - __bfloat162float(h1.y));
            __nv_bfloat162 l2 = __floats2bfloat162_rn(b.x - __bfloat162float(h2.x), b.y - __bfloat162float(h2.y));
            __nv_bfloat162 l3 = __floats2bfloat162_rn(b.z - __bfloat162float(h3.x), b.w - __bfloat162float(h3.y));
            *(uint4*)(base + arow + p * 16)           = make_uint4(bf2u(h0), bf2u(h1), bf2u(h2), bf2u(h3));
            *(uint4*)(base + TILE_SZ + arow + p * 16) = make_uint4(bf2u(l0), bf2u(l1), bf2u(l2), bf2u(l3));
        }
    }
    CP_WAIT0();
    __syncthreads();

    for (int ch = 0; ch < 24; ch++) {
        const int cur = ch & 1;
        char* curbuf = smem + BUF0_OFF + cur * BUF_SZ;
        char* nxtbuf = smem + BUF0_OFF + (1 - cur) * BUF_SZ;
        const unsigned nxtu = sb + BUF0_OFF + (1 - cur) * BUF_SZ;

        if (ch < 23) {
            const int k0 = (ch + 1) * 32;
            const float4* xp = (const float4*)(xrow + k0);
#pragma unroll
            for (int p = 0; p < 4; p++) xv[p] = xp[p];
            stage_bf_pair(nxtu + 2 * TILE_SZ + arow, nxtu + 3 * TILE_SZ + arow,
                          whr + k0, wlr + k0);
            CP_COMMIT();
        }

        compute_chunk(curbuf, wm, wn, c);

        if (ch < 23) {
#pragma unroll
            for (int p = 0; p < 2; p++) {
                float4 a = xv[2 * p], b = xv[2 * p + 1];
                __nv_bfloat162 h0 = __floats2bfloat162_rn(a.x, a.y);
                __nv_bfloat162 h1 = __floats2bfloat162_rn(a.z, a.w);
                __nv_bfloat162 h2 = __floats2bfloat162_rn(b.x, b.y);
                __nv_bfloat162 h3 = __floats2bfloat162_rn(b.z, b.w);
                __nv_bfloat162 l0 = __floats2bfloat162_rn(a.x - __bfloat162float(h0.x), a.y - __bfloat162float(h0.y));
                __nv_bfloat162 l1 = __floats2bfloat162_rn(a.z - __bfloat162float(h1.x), a.w - __bfloat162float(h1.y));
                __nv_bfloat162 l2 = __floats2bfloat162_rn(b.x - __bfloat162float(h2.x), b.y - __bfloat162float(h2.y));
                __nv_bfloat162 l3 = __floats2bfloat162_rn(b.z - __bfloat162float(h3.x), b.w - __bfloat162float(h3.y));
                *(uint4*)(nxtbuf + arow + p * 16)           = make_uint4(bf2u(h0), bf2u(h1), bf2u(h2), bf2u(h3));
                *(uint4*)(nxtbuf + TILE_SZ + arow + p * 16) = make_uint4(bf2u(l0), bf2u(l1), bf2u(l2), bf2u(l3));
            }
            CP_WAIT0();
        }
        __syncthreads();
    }

    // epilogue: dump accumulators, bias + mish + split, store
    float* Cs = (float*)(smem + BUF0_OFF);
#pragma unroll
    for (int i = 0; i < 2; i++)
#pragma unroll
        for (int j = 0; j < 4; j++)
            wmma::store_matrix_sync(Cs + (wm * 32 + i * 16) * EPI_LD + wn * 64 + j * 16,
                                    c[i][j], EPI_LD, wmma::mem_row_major);
    __syncthreads();

    const float* crow = Cs + r * EPI_LD + half * 64;
    const float* bptr = bias + half * 64;
    bf16* dh = g_Hhi + (size_t)(m0 + r) * DMODEL + n0 + half * 64;
    bf16* dl = g_Hlo + (size_t)(m0 + r) * DMODEL + n0 + half * 64;
#pragma unroll
    for (int blk = 0; blk < 8; blk++) {
        unsigned hw[4], lw[4];
#pragma unroll
        for (int e = 0; e < 4; e++) {
            float v0 = mish_f(crow[blk * 8 + 2 * e]     + bptr[blk * 8 + 2 * e]);
            float v1 = mish_f(crow[blk * 8 + 2 * e + 1] + bptr[blk * 8 + 2 * e + 1]);
            __nv_bfloat162 hh = __floats2bfloat162_rn(v0, v1);
            __nv_bfloat162 ll = __floats2bfloat162_rn(v0 - __bfloat162float(hh.x),
                                                      v1 - __bfloat162float(hh.y));
            hw[e] = bf2u(hh); lw[e] = bf2u(ll);
        }
        *(uint4*)(dh + blk * 8) = make_uint4(hw[0], hw[1], hw[2], hw[3]);
        *(uint4*)(dl + blk * 8) = make_uint4(lw[0], lw[1], lw[2], lw[3]);
    }
}

// ---------------------------------------------------------------------------
// Kernel B: QK = H @ [Wq|Wk] + bias -> g_QK fp32.  grid 1024, 256 thr.
// ---------------------------------------------------------------------------
__global__ __launch_bounds__(256, 2) void k_gemmB(const float* __restrict__ bq,
                                                  const float* __restrict__ bk)
{
    extern __shared__ char smem[];
    const unsigned sb = s2u(smem);
    float* bias = (float*)smem;
    const int tid = threadIdx.x, wid = tid >> 5;
    const int wm = wid & 3, wn = wid >> 2;
    const int m0 = blockIdx.x * 128;
    const int r = tid >> 1, half = tid & 1;

    if (tid < 128) bias[tid] = (tid < 64) ? bq[tid] : bk[tid - 64];

    FragC c[2][4];
#pragma unroll
    for (int i = 0; i < 2; i++)
#pragma unroll
        for (int j = 0; j < 4; j++) wmma::fill_fragment(c[i][j], 0.0f);

    const bf16* ahr = g_Hhi + (size_t)(m0 + r) * DMODEL + half * 16;
    const bf16* alr = g_Hlo + (size_t)(m0 + r) * DMODEL + half * 16;
    const bf16* whr = g_WqkT_hi + (size_t)r * DMODEL + half * 16;
    const bf16* wlr = g_WqkT_lo + (size_t)r * DMODEL + half * 16;
    const unsigned arow = r * TB + half * 32;

    // prologue chunk 0
    stage_bf_pair(sb + BUF0_OFF + arow,               sb + BUF0_OFF + TILE_SZ + arow,     ahr, alr);
    stage_bf_pair(sb + BUF0_OFF + 2 * TILE_SZ + arow, sb + BUF0_OFF + 3 * TILE_SZ + arow, whr, wlr);
    CP_COMMIT();
    CP_WAIT0();
    __syncthreads();

    for (int ch = 0; ch < 24; ch++) {
        const int cur = ch & 1;
        char* curbuf = smem + BUF0_OFF + cur * BUF_SZ;
        const unsigned nxtu = sb + BUF0_OFF + (1 - cur) * BUF_SZ;

        if (ch < 23) {
            const int k0 = (ch + 1) * 32;
            stage_bf_pair(nxtu + arow,               nxtu + TILE_SZ + arow,     ahr + k0, alr + k0);
            stage_bf_pair(nxtu + 2 * TILE_SZ + arow, nxtu + 3 * TILE_SZ + arow, whr + k0, wlr + k0);
            CP_COMMIT();
        }
        compute_chunk(curbuf, wm, wn, c);
        if (ch < 23) CP_WAIT0();
        __syncthreads();
    }

    float* Cs = (float*)(smem + BUF0_OFF);
#pragma unroll
    for (int i = 0; i < 2; i++)
#pragma unroll
        for (int j = 0; j < 4; j++)
            wmma::store_matrix_sync(Cs + (wm * 32 + i * 16) * EPI_LD + wn * 64 + j * 16,
                                    c[i][j], EPI_LD, wmma::mem_row_major);
    __syncthreads();

    const float* crow = Cs + r * EPI_LD + half * 64;
    const float* bptr = bias + half * 64;
    float* orow = g_QK + (size_t)(m0 + r) * 128 + half * 64;
#pragma unroll
    for (int blk = 0; blk < 16; blk++) {
        float4 o;
        o.x = crow[blk * 4 + 0] + bptr[blk * 4 + 0];
        o.y = crow[blk * 4 + 1] + bptr[blk * 4 + 1];
        o.z = crow[blk * 4 + 2] + bptr[blk * 4 + 2];
        o.w = crow[blk * 4 + 3] + bptr[blk * 4 + 3];
        *(float4*)(orow + blk * 4) = o;
    }
}

// ---------------------------------------------------------------------------
// Kernel C: per-batch scores (4x4 register tiles) + promotion + gather.
// ---------------------------------------------------------------------------
__global__ __launch_bounds__(256) void k_scores_gather(
    const float* __restrict__ Wp, const float* __restrict__ bp,
    const int* __restrict__ indices, float* __restrict__ out)
{
    __shared__ float q_s[64][65];
    __shared__ float k_s[64][65];
    __shared__ float s_s[64][64];
    __shared__ float prom2[24];

    const int b = blockIdx.x, tid = threadIdx.x;
    for (int i = tid; i < 64 * 64; i += 256) {
        int rr = i >> 6, cc = i & 63;
        const float* row = &g_QK[((size_t)b * 64 + rr) * 128];
        q_s[rr][cc] = row[cc];
        k_s[rr][cc] = row[64 + cc];
    }
    __syncthreads();

    {
        const int tx = tid & 15, ty = tid >> 4;
        const int i0 = ty * 4, j0 = tx * 4;
        float acc[4][4] = {};
#pragma unroll 16
        for (int d = 0; d < 64; d++) {
            float qv[4], kv[4];
#pragma unroll
            for (int a = 0; a < 4; a++) { qv[a] = q_s[i0 + a][d]; kv[a] = k_s[j0 + a][d]; }
#pragma unroll
            for (int a = 0; a < 4; a++)
#pragma unroll
                for (int e = 0; e < 4; e++) acc[a][e] += qv[a] * kv[e];
        }
#pragma unroll
        for (int a = 0; a < 4; a++)
#pragma unroll
            for (int e = 0; e < 4; e++) s_s[i0 + a][j0 + e] = acc[a][e] * 0.125f;
    }

    if (tid < 24) {
        int jr = 56 + tid / 3, cc = tid % 3;
        float acc = bp[cc] + bp[3];
#pragma unroll
        for (int d = 0; d < 64; d++)
            acc += k_s[jr][d] * (Wp[d * 4 + cc] + Wp[d * 4 + 3]);
        prom2[tid] = acc;
    }
    __syncthreads();

    for (int t = tid; t < 1858; t += 256) {
        int id = indices[t];
        float v;
        if (id < 4096) v = s_s[id >> 6][id & 63];
        else {
            int p = id - 4096, i = p / 3;
            v = s_s[48 + (i >> 3)][56 + (i & 7)] + prom2[p % 24];
        }
        out[(size_t)b * 1858 + t] = v;
    }
}

// ---------------------------------------------------------------------------
extern "C" void kernel_launch(void* const* d_in, const int* in_sizes, int n_in,
                              void* d_out, int out_size)
{
    const float* x  = (const float*)d_in[0];
    const float* W1 = (const float*)d_in[1];
    const float* b1 = (const float*)d_in[2];
    const float* Wq = (const float*)d_in[3];
    const float* bq = (const float*)d_in[4];
    const float* Wk = (const float*)d_in[5];
    const float* bk = (const float*)d_in[6];
    const float* Wp = (const float*)d_in[7];
    const float* bp = (const float*)d_in[8];
    const int*  idx = (const int*)d_in[9];

    cudaFuncSetAttribute(k_gemmA, cudaFuncAttributeMaxDynamicSharedMemorySize, SMEM_BYTES);
    cudaFuncSetAttribute(k_gemmB, cudaFuncAttributeMaxDynamicSharedMemorySize, SMEM_BYTES);

    k_wconv<<<dim3(24, 24), dim3(32, 8)>>>(W1, 768, 0);
    k_wconv<<<dim3(2, 24),  dim3(32, 8)>>>(Wq, 64, 1);
    k_wconv<<<dim3(2, 24),  dim3(32, 8)>>>(Wk, 64, 2);

    k_gemmA<<<dim3(6, 1024), 256, SMEM_BYTES>>>(x, b1);
    k_gemmB<<<1024, 256, SMEM_BYTES>>>(bq, bk);
    k_scores_gather<<<B_BATCH, 256>>>(Wp, bp, idx, (float*)d_out);
}